// round 4
// baseline (speedup 1.0000x reference)
#include <cuda_runtime.h>
#include <math.h>

#define B 1024
#define D 64
#define O 64
#define M 1024
#define DELTA_F 0.13533528323661270f   // exp(-2)

// ------------------------- device scratch (no mallocs) -------------------------
__device__ float g_sen[B];          // ||x_i||^2
__device__ float g_gterm;           // gsm - sum(gm^2)
__device__ int   g_flag;            // 1 => fast-path hypothesis violated -> run scan
__device__ float g_protos[M * D];
__device__ float g_cents [M * D];
__device__ float g_senc[M];
__device__ float g_cc[M];           // sum(cents^2) per rule
__device__ float g_pp[M];           // sum(protos^2) per rule
__device__ int   g_sup[M];
__device__ int   g_n;
__device__ float g_Gt[B * M];       // Gt[i*M + j] = dot(protos_j, x_i)
__device__ float g_lam[B * M];      // lam[i*M + j] = lambda_{j,i}
__device__ float g_yn[B * O];       // sigmoid(x @ W^T + b)

// ------------------------- K1: sen per row (warp per row) -------------------------
__global__ void k_sen(const float* __restrict__ x) {
    int warp = (blockIdx.x * blockDim.x + threadIdx.x) >> 5;
    int lane = threadIdx.x & 31;
    if (warp >= B) return;
    const float* row = x + warp * D;
    float a = row[lane], b = row[lane + 32];
    float s = a * a + b * b;
    #pragma unroll
    for (int o = 16; o > 0; o >>= 1) s += __shfl_down_sync(0xffffffffu, s, o);
    if (lane == 0) g_sen[warp] = s;
}

// ------------------------- K2: g_term, flag reset -------------------------
__global__ void k_gterm(const float* __restrict__ x) {
    __shared__ float part[16][64];
    __shared__ float red[32];
    __shared__ float gsq[64];
    int t = threadIdx.x;          // 1024 threads
    int d = t & 63, g = t >> 6;   // 16 groups of 64 columns
    float s = 0.f;
    for (int r = g; r < B; r += 16) s += x[r * D + d];
    part[g][d] = s;

    // sum of sen (1024 elements, one per thread)
    float ss = g_sen[t];
    #pragma unroll
    for (int o = 16; o > 0; o >>= 1) ss += __shfl_down_sync(0xffffffffu, ss, o);
    if ((t & 31) == 0) red[t >> 5] = ss;
    __syncthreads();
    if (t < 32) {
        float v = red[t];
        #pragma unroll
        for (int o = 16; o > 0; o >>= 1) v += __shfl_down_sync(0xffffffffu, v, o);
        if (t == 0) red[0] = v;
    }
    __syncthreads();
    if (t < 64) {
        float cs = 0.f;
        #pragma unroll
        for (int gg = 0; gg < 16; gg++) cs += part[gg][t];
        float gm = cs / (1048576.0f);         // (colsum/B)/B
        gsq[t] = gm * gm;
    }
    __syncthreads();
    if (t == 0) {
        float sq = 0.f;
        for (int dd = 0; dd < 64; dd++) sq += gsq[dd];
        float gsm = red[0] / 1048576.0f;      // (sensum/B)/B
        g_gterm = gsm - sq;
        g_flag = 0;
        g_n = B;                              // fast-path rule count
    }
}

// ------------------------- K2b: fast-path state init -------------------------
__global__ void k_init_state(const float* __restrict__ x) {
    int k = blockIdx.x * blockDim.x + threadIdx.x;
    if (k < M * D) { float v = x[k]; g_protos[k] = v; g_cents[k] = v; }
    if (k < M) {
        float s = g_sen[k];
        g_senc[k] = s; g_cc[k] = s; g_pp[k] = s; g_sup[k] = 1;
    }
}

// ------------------------- K3: Gram x@x^T + all-create verification -------------------------
// 64x64 tile, 4x4 outputs/thread (row stride 16), float4 LDS with XOR swizzle
// (col' = col ^ (row&15)): b-loads hit 8 distinct 16B bank-groups per phase
// (conflict-free), a-loads are warp-broadcast. 8 LDS.128 : 64 FFMA per d4-step.
__global__ void __launch_bounds__(256) k_gram_verify(const float* __restrict__ x) {
    __shared__ float4 xi[64][16];
    __shared__ float4 xj[64][16];
    int lt = threadIdx.x;
    int tx = lt & 15, ty = lt >> 4;
    int i0 = blockIdx.y * 64, j0 = blockIdx.x * 64;
    const float4* xv = reinterpret_cast<const float4*>(x);
    #pragma unroll
    for (int k = 0; k < 4; k++) {
        int idx = lt + k * 256;
        int r = idx >> 4, c = idx & 15;
        xi[r][c ^ (r & 15)] = xv[(i0 + r) * 16 + c];
        xj[r][c ^ (r & 15)] = xv[(j0 + r) * 16 + c];
    }
    __syncthreads();
    float acc[4][4] = {};
    #pragma unroll
    for (int d4 = 0; d4 < 16; d4++) {
        float4 a[4], bb[4];
        #pragma unroll
        for (int r = 0; r < 4; r++) a[r]  = xi[ty + 16 * r][d4 ^ ty];
        #pragma unroll
        for (int r = 0; r < 4; r++) bb[r] = xj[tx + 16 * r][d4 ^ tx];
        #pragma unroll
        for (int ra = 0; ra < 4; ra++)
            #pragma unroll
            for (int rb = 0; rb < 4; rb++) {
                acc[ra][rb] += a[ra].x * bb[rb].x + a[ra].y * bb[rb].y
                             + a[ra].z * bb[rb].z + a[ra].w * bb[rb].w;
            }
    }
    // verification: with all-create state, stau_j == |g_term|/2; create requires d2 > 2*stau.
    // flag with 3x margin so any borderline pair routes to the exact scan.
    float thr = 3.0f * fabsf(g_gterm);
    int bad = 0;
    #pragma unroll
    for (int ra = 0; ra < 4; ra++) {
        int i = i0 + ty + 16 * ra;
        float si = g_sen[i];
        #pragma unroll
        for (int rb = 0; rb < 4; rb++) {
            int j = j0 + tx + 16 * rb;
            float v = acc[ra][rb];
            g_Gt[i * M + j] = v;
            bad |= (i != j) && (si + g_sen[j] - 2.0f * v < thr);
        }
    }
    if (bad) atomicOr(&g_flag, 1);
}

// ------------------------- K4: exact sequential scan (fallback, normally skipped) -------------------------
__global__ void __launch_bounds__(1024, 1) k_scan_fallback(const float* __restrict__ x) {
    if (g_flag == 0) return;
    __shared__ float xs[64];
    __shared__ float red_val[32];
    __shared__ int   red_idx[32];
    __shared__ int s_n, s_w, s_create;
    __shared__ float s_sf;
    int t = threadIdx.x;
    if (t == 0) s_n = 0;
    __syncthreads();
    float gterm = g_gterm;
    for (int i = 0; i < B; i++) {
        if (t < 64) xs[t] = x[i * D + t];
        __syncthreads();
        int n = s_n;
        float dens;
        if (t < n) {
            float dist = 0.f;
            #pragma unroll 8
            for (int d = 0; d < 64; d++) { float v = xs[d] - g_protos[t * D + d]; dist += v * v; }
            float stau = fabsf(gterm + g_senc[t] - g_cc[t]) * 0.5f;
            dens = expf(-dist / stau);
        } else dens = -INFINITY;
        float v = dens; int idx = t;
        #pragma unroll
        for (int o = 16; o > 0; o >>= 1) {
            float ov = __shfl_down_sync(0xffffffffu, v, o);
            int   oi = __shfl_down_sync(0xffffffffu, idx, o);
            if (ov > v || (ov == v && oi < idx)) { v = ov; idx = oi; }
        }
        if ((t & 31) == 0) { red_val[t >> 5] = v; red_idx[t >> 5] = idx; }
        __syncthreads();
        if (t < 32) {
            v = red_val[t]; idx = red_idx[t];
            #pragma unroll
            for (int o = 16; o > 0; o >>= 1) {
                float ov = __shfl_down_sync(0xffffffffu, v, o);
                int   oi = __shfl_down_sync(0xffffffffu, idx, o);
                if (ov > v || (ov == v && oi < idx)) { v = ov; idx = oi; }
            }
            if (t == 0) {
                int create = (n == 0) || (v < DELTA_F);
                int w = create ? min(n, M - 1) : idx;
                int supn = create ? 1 : (g_sup[w] + 1);
                g_sup[w] = supn;
                s_w = w; s_create = create; s_sf = (float)supn;
                if (create) s_n = min(n + 1, M);
            }
        }
        __syncthreads();
        int w = s_w; float sf = s_sf; int create = s_create;
        if (t < 64) {
            float xiv = xs[t];
            float p = g_protos[w * D + t];
            float c = g_cents[w * D + t];
            g_protos[w * D + t] = create ? xiv : p;
            g_cents [w * D + t] = create ? xiv : (c + (xiv - c) / sf);
        }
        __syncthreads();
        if (t < 32) {
            float a = g_cents[w * D + t], b2 = g_cents[w * D + t + 32];
            float s = a * a + b2 * b2;
            #pragma unroll
            for (int o = 16; o > 0; o >>= 1) s += __shfl_down_sync(0xffffffffu, s, o);
            if (t == 0) {
                float si = g_sen[i];
                float sc = g_senc[w];
                g_senc[w] = create ? si : (sc + (si - sc) / sf);
                g_cc[w] = s;
            }
        }
        __syncthreads();
    }
    if (t == 0) g_n = s_n;
    __syncthreads();
    // recompute pp and Gt from final protos (slow; only on fallback)
    for (int j = t; j < M; j += 1024) {
        float s = 0.f;
        for (int d = 0; d < 64; d++) { float p = g_protos[j * D + d]; s += p * p; }
        g_pp[j] = s;
    }
    for (int k = t; k < B * M; k += 1024) {
        int i = k >> 10, j = k & (M - 1);
        float s = 0.f;
        for (int d = 0; d < 64; d++) s += g_protos[j * D + d] * x[i * D + d];
        g_Gt[k] = s;
    }
}

// ------------------------- K5: dens -> lambda (block per column i), stau inline,
//                           exp-skip for underflowed entries, y_n fused in tail ----
__global__ void k_lambda(const float* __restrict__ x, const float* __restrict__ W,
                         const float* __restrict__ b) {
    __shared__ float red[8];
    __shared__ float s_inv;
    __shared__ float xs[64];
    int i = blockIdx.x, t = threadIdx.x;       // 256 threads
    if (t < 64) xs[t] = x[i * D + t];
    float sen_i = g_sen[i];
    float gterm = g_gterm;
    int n = g_n;
    float dv[4];
    float local = 0.f;
    #pragma unroll
    for (int k = 0; k < 4; k++) {
        int j = t + k * 256;
        float stau = fabsf(gterm + g_senc[j] - g_cc[j]) * 0.5f;
        float d2 = fmaxf(sen_i + g_pp[j] - 2.0f * g_Gt[i * M + j], 0.0f);
        float arg = -d2 / stau;
        float dens = 0.0f;
        if (j < n && arg > -85.0f) dens = expf(arg);   // skip MUFU for underflowed terms
        dv[k] = dens;
        local += dens;
    }
    #pragma unroll
    for (int o = 16; o > 0; o >>= 1) local += __shfl_down_sync(0xffffffffu, local, o);
    if ((t & 31) == 0) red[t >> 5] = local;
    __syncthreads();
    if (t < 8) {
        float v = red[t];
        #pragma unroll
        for (int o = 4; o > 0; o >>= 1) v += __shfl_down_sync(0xffu, v, o);
        if (t == 0) s_inv = 1.0f / v;
    }
    __syncthreads();
    float inv = s_inv;
    #pragma unroll
    for (int k = 0; k < 4; k++) g_lam[i * M + t + k * 256] = dv[k] * inv;
    // fused y_n = sigmoid(x W^T + b) for this row (xs published by the syncthreads above)
    if (t < 64) {
        float z = b[t];
        #pragma unroll
        for (int d = 0; d < 64; d++) z += xs[d] * W[t * D + d];
        g_yn[i * O + t] = 1.0f / (1.0f + expf(-z));
    }
}

// ------------------------- K7: output broadcast write (HBM-store-bound) -------------------------
__global__ void k_out(float4* __restrict__ out) {
    __shared__ float  lam_s[64];
    __shared__ float4 yn_s[16];
    int i = blockIdx.x, c = blockIdx.y, t = threadIdx.x;   // 256 threads, c in [0,16)
    if (t < 64) lam_s[t] = g_lam[i * M + c * 64 + t];
    if (t < 16) yn_s[t] = reinterpret_cast<const float4*>(g_yn)[i * 16 + t];
    __syncthreads();
    float4* dst = out + (size_t)i * 16384 + (size_t)c * 1024;
    #pragma unroll
    for (int k = 0; k < 4; k++) {
        int f = t + k * 256;                 // [0,1024): 1024 float4 per block
        float l = lam_s[f >> 4];
        float4 v = yn_s[f & 15];
        v.x *= l; v.y *= l; v.z *= l; v.w *= l;
        __stcs(dst + f, v);                  // streaming store: write-once data, spare L2
    }
}

// ------------------------- launch -------------------------
extern "C" void kernel_launch(void* const* d_in, const int* in_sizes, int n_in,
                              void* d_out, int out_size) {
    const float* x = (const float*)d_in[0];
    const float* W = (const float*)d_in[1];
    const float* b = (const float*)d_in[2];
    float4* out = (float4*)d_out;

    k_sen<<<B / 8, 256>>>(x);
    k_gterm<<<1, 1024>>>(x);
    k_init_state<<<(M * D + 255) / 256, 256>>>(x);
    k_gram_verify<<<dim3(M / 64, B / 64), 256>>>(x);
    k_scan_fallback<<<1, 1024>>>(x);
    k_lambda<<<B, 256>>>(x, W, b);
    k_out<<<dim3(B, 16), 256>>>(out);
}

// round 6
// speedup vs baseline: 1.2721x; 1.2721x over previous
#include <cuda_runtime.h>
#include <math.h>

#define B 1024
#define D 64
#define O 64
#define M 1024
#define DELTA_F 0.13533528323661270f   // exp(-2)

// ------------------------- device scratch (no mallocs) -------------------------
__device__ float g_sen[B];          // ||x_i||^2
__device__ float g_gterm;           // gsm - sum(gm^2)
__device__ int   g_flag;            // 1 => fast-path hypothesis violated -> run scan
__device__ float g_protos[M * D];
__device__ float g_cents [M * D];
__device__ float g_senc[M];
__device__ float g_cc[M];           // sum(cents^2) per rule
__device__ float g_pp[M];           // sum(protos^2) per rule
__device__ int   g_sup[M];
__device__ int   g_n;
__device__ float g_Gt[B * M];       // Gt[i*M + j] = dot(protos_j, x_i)

// ------------------------- K1: sen per row (warp per row) -------------------------
__global__ void k_sen(const float* __restrict__ x) {
    int warp = (blockIdx.x * blockDim.x + threadIdx.x) >> 5;
    int lane = threadIdx.x & 31;
    if (warp >= B) return;
    const float* row = x + warp * D;
    float a = row[lane], b = row[lane + 32];
    float s = a * a + b * b;
    #pragma unroll
    for (int o = 16; o > 0; o >>= 1) s += __shfl_down_sync(0xffffffffu, s, o);
    if (lane == 0) g_sen[warp] = s;
}

// ------------------------- K2: g_term, flag reset -------------------------
__global__ void k_gterm(const float* __restrict__ x) {
    __shared__ float part[16][64];
    __shared__ float red[32];
    __shared__ float gsq[64];
    int t = threadIdx.x;          // 1024 threads
    int d = t & 63, g = t >> 6;   // 16 groups of 64 columns
    float s = 0.f;
    for (int r = g; r < B; r += 16) s += x[r * D + d];
    part[g][d] = s;

    float ss = g_sen[t];
    #pragma unroll
    for (int o = 16; o > 0; o >>= 1) ss += __shfl_down_sync(0xffffffffu, ss, o);
    if ((t & 31) == 0) red[t >> 5] = ss;
    __syncthreads();
    if (t < 32) {
        float v = red[t];
        #pragma unroll
        for (int o = 16; o > 0; o >>= 1) v += __shfl_down_sync(0xffffffffu, v, o);
        if (t == 0) red[0] = v;
    }
    __syncthreads();
    if (t < 64) {
        float cs = 0.f;
        #pragma unroll
        for (int gg = 0; gg < 16; gg++) cs += part[gg][t];
        float gm = cs / (1048576.0f);
        gsq[t] = gm * gm;
    }
    __syncthreads();
    if (t == 0) {
        float sq = 0.f;
        for (int dd = 0; dd < 64; dd++) sq += gsq[dd];
        float gsm = red[0] / 1048576.0f;
        g_gterm = gsm - sq;
        g_flag = 0;
        g_n = B;
    }
}

// ------------------------- K2b: fast-path state init -------------------------
__global__ void k_init_state(const float* __restrict__ x) {
    int k = blockIdx.x * blockDim.x + threadIdx.x;
    if (k < M * D) { float v = x[k]; g_protos[k] = v; g_cents[k] = v; }
    if (k < M) {
        float s = g_sen[k];
        g_senc[k] = s; g_cc[k] = s; g_pp[k] = s; g_sup[k] = 1;
    }
}

// ------------------------- K3: Gram x@x^T (triangular blocks) + verification ----
// 64x64 tile, 4x4 outputs/thread, float4 XOR-swizzled SMEM. Only upper-triangular
// block grid (136 blocks); off-diagonal tiles store the transpose too.
__global__ void __launch_bounds__(256) k_gram_verify(const float* __restrict__ x) {
    __shared__ float4 xi[64][16];
    __shared__ float4 xj[64][16];
    // triangular decode: blockIdx.x -> (by, bx) with bx >= by, 16x16 tile grid
    int rem = blockIdx.x, by = 0;
    while (rem >= 16 - by) { rem -= 16 - by; by++; }
    int bx = by + rem;
    int i0 = by * 64, j0 = bx * 64;
    int lt = threadIdx.x;
    int tx = lt & 15, ty = lt >> 4;
    const float4* xv = reinterpret_cast<const float4*>(x);
    #pragma unroll
    for (int k = 0; k < 4; k++) {
        int idx = lt + k * 256;
        int r = idx >> 4, c = idx & 15;
        xi[r][c ^ (r & 15)] = xv[(i0 + r) * 16 + c];
        xj[r][c ^ (r & 15)] = xv[(j0 + r) * 16 + c];
    }
    __syncthreads();
    float acc[4][4] = {};
    #pragma unroll
    for (int d4 = 0; d4 < 16; d4++) {
        float4 a[4], bb[4];
        #pragma unroll
        for (int r = 0; r < 4; r++) a[r]  = xi[ty + 16 * r][d4 ^ ty];
        #pragma unroll
        for (int r = 0; r < 4; r++) bb[r] = xj[tx + 16 * r][d4 ^ tx];
        #pragma unroll
        for (int ra = 0; ra < 4; ra++)
            #pragma unroll
            for (int rb = 0; rb < 4; rb++) {
                acc[ra][rb] += a[ra].x * bb[rb].x + a[ra].y * bb[rb].y
                             + a[ra].z * bb[rb].z + a[ra].w * bb[rb].w;
            }
    }
    // verification: with all-create state, stau_j == |g_term|/2; create requires d2 > 2*stau.
    // flag with 3x margin so any borderline pair routes to the exact scan.
    float thr = 3.0f * fabsf(g_gterm);
    int bad = 0;
    #pragma unroll
    for (int ra = 0; ra < 4; ra++) {
        int i = i0 + ty + 16 * ra;
        float si = g_sen[i];
        #pragma unroll
        for (int rb = 0; rb < 4; rb++) {
            int j = j0 + tx + 16 * rb;
            float v = acc[ra][rb];
            g_Gt[i * M + j] = v;
            bad |= (i != j) && (si + g_sen[j] - 2.0f * v < thr);
        }
    }
    if (bx != by) {
        #pragma unroll
        for (int ra = 0; ra < 4; ra++) {
            int i = i0 + ty + 16 * ra;
            #pragma unroll
            for (int rb = 0; rb < 4; rb++) {
                int j = j0 + tx + 16 * rb;
                g_Gt[j * M + i] = acc[ra][rb];   // symmetric fill
            }
        }
    }
    if (bad) atomicOr(&g_flag, 1);
}

// ------------------------- K4: exact sequential scan (fallback, normally skipped) -------------------------
__global__ void __launch_bounds__(1024, 1) k_scan_fallback(const float* __restrict__ x) {
    if (g_flag == 0) return;
    __shared__ float xs[64];
    __shared__ float red_val[32];
    __shared__ int   red_idx[32];
    __shared__ int s_n, s_w, s_create;
    __shared__ float s_sf;
    int t = threadIdx.x;
    if (t == 0) s_n = 0;
    __syncthreads();
    float gterm = g_gterm;
    for (int i = 0; i < B; i++) {
        if (t < 64) xs[t] = x[i * D + t];
        __syncthreads();
        int n = s_n;
        float dens;
        if (t < n) {
            float dist = 0.f;
            #pragma unroll 8
            for (int d = 0; d < 64; d++) { float v = xs[d] - g_protos[t * D + d]; dist += v * v; }
            float stau = fabsf(gterm + g_senc[t] - g_cc[t]) * 0.5f;
            dens = expf(-dist / stau);
        } else dens = -INFINITY;
        float v = dens; int idx = t;
        #pragma unroll
        for (int o = 16; o > 0; o >>= 1) {
            float ov = __shfl_down_sync(0xffffffffu, v, o);
            int   oi = __shfl_down_sync(0xffffffffu, idx, o);
            if (ov > v || (ov == v && oi < idx)) { v = ov; idx = oi; }
        }
        if ((t & 31) == 0) { red_val[t >> 5] = v; red_idx[t >> 5] = idx; }
        __syncthreads();
        if (t < 32) {
            v = red_val[t]; idx = red_idx[t];
            #pragma unroll
            for (int o = 16; o > 0; o >>= 1) {
                float ov = __shfl_down_sync(0xffffffffu, v, o);
                int   oi = __shfl_down_sync(0xffffffffu, idx, o);
                if (ov > v || (ov == v && oi < idx)) { v = ov; idx = oi; }
            }
            if (t == 0) {
                int create = (n == 0) || (v < DELTA_F);
                int w = create ? min(n, M - 1) : idx;
                int supn = create ? 1 : (g_sup[w] + 1);
                g_sup[w] = supn;
                s_w = w; s_create = create; s_sf = (float)supn;
                if (create) s_n = min(n + 1, M);
            }
        }
        __syncthreads();
        int w = s_w; float sf = s_sf; int create = s_create;
        if (t < 64) {
            float xiv = xs[t];
            float p = g_protos[w * D + t];
            float c = g_cents[w * D + t];
            g_protos[w * D + t] = create ? xiv : p;
            g_cents [w * D + t] = create ? xiv : (c + (xiv - c) / sf);
        }
        __syncthreads();
        if (t < 32) {
            float a = g_cents[w * D + t], b2 = g_cents[w * D + t + 32];
            float s = a * a + b2 * b2;
            #pragma unroll
            for (int o = 16; o > 0; o >>= 1) s += __shfl_down_sync(0xffffffffu, s, o);
            if (t == 0) {
                float si = g_sen[i];
                float sc = g_senc[w];
                g_senc[w] = create ? si : (sc + (si - sc) / sf);
                g_cc[w] = s;
            }
        }
        __syncthreads();
    }
    if (t == 0) g_n = s_n;
    __syncthreads();
    // recompute pp and Gt from final protos (slow; only on fallback)
    for (int j = t; j < M; j += 1024) {
        float s = 0.f;
        for (int d = 0; d < 64; d++) { float p = g_protos[j * D + d]; s += p * p; }
        g_pp[j] = s;
    }
    for (int k = t; k < B * M; k += 1024) {
        int i = k >> 10, j = k & (M - 1);
        float s = 0.f;
        for (int d = 0; d < 64; d++) s += g_protos[j * D + d] * x[i * D + d];
        g_Gt[k] = s;
    }
}

// ------------------------- K5: fused lambda + y_n + output (block per row i) ----
__global__ void __launch_bounds__(256) k_lamout(const float* __restrict__ x,
                                                const float* __restrict__ W,
                                                const float* __restrict__ b,
                                                float4* __restrict__ out) {
    __shared__ float lam_s[1024];
    __shared__ float ynp[4][64];
    __shared__ __align__(16) float yn_f[64];
    __shared__ __align__(16) float xs[64];
    __shared__ float red[8];
    __shared__ float s_inv;
    int i = blockIdx.x, t = threadIdx.x;       // 256 threads
    if (t < 64) xs[t] = x[i * D + t];
    __syncthreads();
    // --- dens over all j, exp-skip for underflowed terms ---
    float sen_i = g_sen[i];
    float gterm = g_gterm;
    int n = g_n;
    float dv[4];
    float local = 0.f;
    #pragma unroll
    for (int k = 0; k < 4; k++) {
        int j = t + k * 256;
        float stau = fabsf(gterm + g_senc[j] - g_cc[j]) * 0.5f;
        float d2 = fmaxf(sen_i + g_pp[j] - 2.0f * g_Gt[i * M + j], 0.0f);
        float arg = -d2 / stau;
        float dens = 0.0f;
        if (j < n && arg > -85.0f) dens = expf(arg);
        dv[k] = dens;
        local += dens;
    }
    #pragma unroll
    for (int o = 16; o > 0; o >>= 1) local += __shfl_down_sync(0xffffffffu, local, o);
    if ((t & 31) == 0) red[t >> 5] = local;
    // --- y_n partials, balanced over all 256 threads (4 threads per output) ---
    {
        int o = t & 63, q = t >> 6;
        const float4* Wv = reinterpret_cast<const float4*>(W);
        const float4* xv4 = reinterpret_cast<const float4*>(xs);
        float z = 0.f;
        #pragma unroll
        for (int m = 0; m < 4; m++) {
            float4 w4 = Wv[o * 16 + q * 4 + m];
            float4 xx = xv4[q * 4 + m];
            z += w4.x * xx.x + w4.y * xx.y + w4.z * xx.z + w4.w * xx.w;
        }
        ynp[q][o] = z;
    }
    __syncthreads();
    if (t < 8) {
        float v = red[t];
        #pragma unroll
        for (int o = 4; o > 0; o >>= 1) v += __shfl_down_sync(0xffu, v, o);
        if (t == 0) s_inv = 1.0f / v;
    } else if (t >= 64 && t < 128) {
        int o = t - 64;
        float z = ynp[0][o] + ynp[1][o] + ynp[2][o] + ynp[3][o] + b[o];
        yn_f[o] = 1.0f / (1.0f + expf(-z));
    }
    __syncthreads();
    float inv = s_inv;
    #pragma unroll
    for (int k = 0; k < 4; k++) lam_s[t + k * 256] = dv[k] * inv;
    __syncthreads();
    // --- store 16384 float4 for this row; yn index (f&15)==t&15 is loop-invariant ---
    const float4* yn4 = reinterpret_cast<const float4*>(yn_f);
    float4 base = yn4[t & 15];
    float4* dst = out + (size_t)i * 16384 + t;
    int r0 = t >> 4;
    #pragma unroll
    for (int k = 0; k < 64; k++) {
        float l = lam_s[r0 + 16 * k];
        float4 v;
        v.x = base.x * l; v.y = base.y * l; v.z = base.z * l; v.w = base.w * l;
        __stcs(dst + 256 * k, v);            // streaming store: write-once data
    }
}

// ------------------------- launch -------------------------
extern "C" void kernel_launch(void* const* d_in, const int* in_sizes, int n_in,
                              void* d_out, int out_size) {
    const float* x = (const float*)d_in[0];
    const float* W = (const float*)d_in[1];
    const float* b = (const float*)d_in[2];
    float4* out = (float4*)d_out;

    k_sen<<<B / 8, 256>>>(x);
    k_gterm<<<1, 1024>>>(x);
    k_init_state<<<(M * D + 255) / 256, 256>>>(x);
    k_gram_verify<<<136, 256>>>(x);
    k_scan_fallback<<<1, 1024>>>(x);
    k_lamout<<<B, 256>>>(x, W, b, out);
}

// round 10
// speedup vs baseline: 1.3871x; 1.0904x over previous
#include <cuda_runtime.h>
#include <math.h>

#define B 1024
#define D 64
#define O 64
#define M 1024
#define DELTA_F 0.13533528323661270f   // exp(-2)

// ------------------------- device scratch (no mallocs) -------------------------
__device__ float g_sen[B];          // ||x_i||^2
__device__ float g_gterm;           // gsm - sum(gm^2)
__device__ int   g_flag;            // 1 => fast-path hypothesis violated -> run scan
__device__ float g_protos[M * D];
__device__ float g_cents [M * D];
__device__ float g_senc[M];
__device__ float g_cc[M];           // sum(cents^2) per rule
__device__ float g_pp[M];           // sum(protos^2) per rule
__device__ int   g_sup[M];
__device__ int   g_n;
__device__ float g_Gt[B * M];       // fallback only: Gt[i*M + j] = dot(protos_j, x_i)

// ------------------------- K1: sen per row (warp per row) -------------------------
__global__ void k_sen(const float* __restrict__ x) {
    int warp = (blockIdx.x * blockDim.x + threadIdx.x) >> 5;
    int lane = threadIdx.x & 31;
    if (warp >= B) return;
    const float* row = x + warp * D;
    float a = row[lane], b = row[lane + 32];
    float s = a * a + b * b;
    #pragma unroll
    for (int o = 16; o > 0; o >>= 1) s += __shfl_down_sync(0xffffffffu, s, o);
    if (lane == 0) g_sen[warp] = s;
}

// ------------------------- K2: g_term, flag reset -------------------------
__global__ void k_gterm(const float* __restrict__ x) {
    __shared__ float part[16][64];
    __shared__ float red[32];
    __shared__ float gsq[64];
    int t = threadIdx.x;          // 1024 threads
    int d = t & 63, g = t >> 6;
    float s = 0.f;
    for (int r = g; r < B; r += 16) s += x[r * D + d];
    part[g][d] = s;

    float ss = g_sen[t];
    #pragma unroll
    for (int o = 16; o > 0; o >>= 1) ss += __shfl_down_sync(0xffffffffu, ss, o);
    if ((t & 31) == 0) red[t >> 5] = ss;
    __syncthreads();
    if (t < 32) {
        float v = red[t];
        #pragma unroll
        for (int o = 16; o > 0; o >>= 1) v += __shfl_down_sync(0xffffffffu, v, o);
        if (t == 0) red[0] = v;
    }
    __syncthreads();
    if (t < 64) {
        float cs = 0.f;
        #pragma unroll
        for (int gg = 0; gg < 16; gg++) cs += part[gg][t];
        float gm = cs / (1048576.0f);
        gsq[t] = gm * gm;
    }
    __syncthreads();
    if (t == 0) {
        float sq = 0.f;
        for (int dd = 0; dd < 64; dd++) sq += gsq[dd];
        float gsm = red[0] / 1048576.0f;
        g_gterm = gsm - sq;
        g_flag = 0;
        g_n = B;
    }
}

// ------------------------- K3: all-pairs verification, FLAG ONLY ---------------
// 32x32 triangular tiles (528 blocks, ~3.5/SM), float4 XOR-swizzled SMEM.
// Condition for fast path: every off-diag pair has d2 > 64|g_term| = 128*stau.
//   * d2 > |g_term| = 2*stau  => reference scan creates a rule at every step
//     (stau_j = |g_term|/2 exactly in the all-create state: senc_j == cc_j bitwise)
//   * d2 > 128*stau => every off-diag reference dens has arg <= -128, and
//     expf(-128) ~ 2.6e-56 < min fp32 subnormal => dens is BITWISE 0.0f. The
//     reference lambda is then exactly the identity (dens_ii/dens_ii == 1.0f),
//     so the fast path may emit it bitwise-exactly.
__global__ void __launch_bounds__(256) k_verify(const float* __restrict__ x) {
    __shared__ float4 xi[32][16];
    __shared__ float4 xj[32][16];
    int rem = blockIdx.x, by = 0;
    while (rem >= 32 - by) { rem -= 32 - by; by++; }
    int bx = by + rem;
    int i0 = by * 32, j0 = bx * 32;
    int lt = threadIdx.x;
    int tx = lt & 15, ty = lt >> 4;
    const float4* xv = reinterpret_cast<const float4*>(x);
    #pragma unroll
    for (int k = 0; k < 2; k++) {
        int idx = lt + k * 256;
        int r = idx >> 4, c = idx & 15;
        xi[r][c ^ (r & 15)] = xv[(i0 + r) * 16 + c];
        xj[r][c ^ (r & 15)] = xv[(j0 + r) * 16 + c];
    }
    __syncthreads();
    float a00 = 0.f, a01 = 0.f, a10 = 0.f, a11 = 0.f;
    #pragma unroll
    for (int d4 = 0; d4 < 16; d4++) {
        float4 a0 = xi[ty][d4 ^ ty];
        float4 a1 = xi[ty + 16][d4 ^ ty];     // (ty+16)&15 == ty
        float4 b0 = xj[tx][d4 ^ tx];
        float4 b1 = xj[tx + 16][d4 ^ tx];
        a00 += a0.x * b0.x + a0.y * b0.y + a0.z * b0.z + a0.w * b0.w;
        a01 += a0.x * b1.x + a0.y * b1.y + a0.z * b1.z + a0.w * b1.w;
        a10 += a1.x * b0.x + a1.y * b0.y + a1.z * b0.z + a1.w * b0.w;
        a11 += a1.x * b1.x + a1.y * b1.y + a1.z * b1.z + a1.w * b1.w;
    }
    float thr = 64.0f * fabsf(g_gterm);
    int ia = i0 + ty, ib = i0 + ty + 16;
    int ja = j0 + tx, jb = j0 + tx + 16;
    float sia = g_sen[ia], sib = g_sen[ib];
    float sja = g_sen[ja], sjb = g_sen[jb];
    int bad = 0;
    bad |= (ia != ja) && (sia + sja - 2.0f * a00 < thr);
    bad |= (ia != jb) && (sia + sjb - 2.0f * a01 < thr);
    bad |= (ib != ja) && (sib + sja - 2.0f * a10 < thr);
    bad |= (ib != jb) && (sib + sjb - 2.0f * a11 < thr);
    if (__syncthreads_or(bad)) {
        if (lt == 0) atomicOr(&g_flag, 1);
    }
}

// ------------------------- K4: exact sequential scan (fallback, normally skipped) ---
__global__ void __launch_bounds__(1024, 1) k_scan_fallback(const float* __restrict__ x) {
    if (g_flag == 0) return;
    __shared__ float xs[64];
    __shared__ float red_val[32];
    __shared__ int   red_idx[32];
    __shared__ int s_n, s_w, s_create;
    __shared__ float s_sf;
    int t = threadIdx.x;
    if (t == 0) s_n = 0;
    __syncthreads();
    float gterm = g_gterm;
    for (int i = 0; i < B; i++) {
        if (t < 64) xs[t] = x[i * D + t];
        __syncthreads();
        int n = s_n;
        float dens;
        if (t < n) {
            float dist = 0.f;
            #pragma unroll 8
            for (int d = 0; d < 64; d++) { float v = xs[d] - g_protos[t * D + d]; dist += v * v; }
            float stau = fabsf(gterm + g_senc[t] - g_cc[t]) * 0.5f;
            dens = expf(-dist / stau);
        } else dens = -INFINITY;
        float v = dens; int idx = t;
        #pragma unroll
        for (int o = 16; o > 0; o >>= 1) {
            float ov = __shfl_down_sync(0xffffffffu, v, o);
            int   oi = __shfl_down_sync(0xffffffffu, idx, o);
            if (ov > v || (ov == v && oi < idx)) { v = ov; idx = oi; }
        }
        if ((t & 31) == 0) { red_val[t >> 5] = v; red_idx[t >> 5] = idx; }
        __syncthreads();
        if (t < 32) {
            v = red_val[t]; idx = red_idx[t];
            #pragma unroll
            for (int o = 16; o > 0; o >>= 1) {
                float ov = __shfl_down_sync(0xffffffffu, v, o);
                int   oi = __shfl_down_sync(0xffffffffu, idx, o);
                if (ov > v || (ov == v && oi < idx)) { v = ov; idx = oi; }
            }
            if (t == 0) {
                int create = (n == 0) || (v < DELTA_F);
                int w = create ? min(n, M - 1) : idx;
                int supn = create ? 1 : (g_sup[w] + 1);
                g_sup[w] = supn;
                s_w = w; s_create = create; s_sf = (float)supn;
                if (create) s_n = min(n + 1, M);
            }
        }
        __syncthreads();
        int w = s_w; float sf = s_sf; int create = s_create;
        if (t < 64) {
            float xiv = xs[t];
            float p = create ? 0.f : g_protos[w * D + t];
            float c = create ? 0.f : g_cents[w * D + t];
            g_protos[w * D + t] = create ? xiv : p;
            g_cents [w * D + t] = create ? xiv : (c + (xiv - c) / sf);
        }
        __syncthreads();
        if (t < 32) {
            float a = g_cents[w * D + t], b2 = g_cents[w * D + t + 32];
            float s = a * a + b2 * b2;
            #pragma unroll
            for (int o = 16; o > 0; o >>= 1) s += __shfl_down_sync(0xffffffffu, s, o);
            if (t == 0) {
                float si = g_sen[i];
                float sc = create ? 0.f : g_senc[w];
                g_senc[w] = create ? si : (sc + (si - sc) / sf);
                g_cc[w] = s;
            }
        }
        __syncthreads();
    }
    if (t == 0) g_n = s_n;
    __syncthreads();
    // recompute pp and Gt from final protos (slow; only on fallback)
    for (int j = t; j < M; j += 1024) {
        float s = 0.f;
        for (int d = 0; d < 64; d++) { float p = g_protos[j * D + d]; s += p * p; }
        g_pp[j] = s;
    }
    for (int k = t; k < B * M; k += 1024) {
        int i = k >> 10, j = k & (M - 1);
        float s = 0.f;
        for (int d = 0; d < 64; d++) s += g_protos[j * D + d] * x[i * D + d];
        g_Gt[k] = s;
    }
}

// ------------------------- K5: fused lambda + y_n + output (block per row i) ----
// Fast path (flag==0): lambda == identity bitwise -> pure y_n / zero stores.
// Fallback (flag==1): exact dens from scan-produced state + Gt.
__global__ void __launch_bounds__(256) k_lamout(const float* __restrict__ x,
                                                const float* __restrict__ W,
                                                const float* __restrict__ b,
                                                float4* __restrict__ out) {
    __shared__ float lam_s[1024];
    __shared__ float ynp[4][64];
    __shared__ __align__(16) float yn_f[64];
    __shared__ __align__(16) float xs[64];
    __shared__ float red[8];
    __shared__ float s_inv;
    int i = blockIdx.x, t = threadIdx.x;       // 256 threads
    if (t < 64) xs[t] = x[i * D + t];
    __syncthreads();
    int flag = g_flag;                          // block-uniform
    // --- y_n partials, balanced over all 256 threads (4 threads per output) ---
    {
        int o = t & 63, q = t >> 6;
        const float4* Wv = reinterpret_cast<const float4*>(W);
        const float4* xv4 = reinterpret_cast<const float4*>(xs);
        float z = 0.f;
        #pragma unroll
        for (int m = 0; m < 4; m++) {
            float4 w4 = Wv[o * 16 + q * 4 + m];
            float4 xx = xv4[q * 4 + m];
            z += w4.x * xx.x + w4.y * xx.y + w4.z * xx.z + w4.w * xx.w;
        }
        ynp[q][o] = z;
    }
    float dv[4];
    if (flag) {
        // --- exact dens over all j (fallback state) ---
        float sen_i = g_sen[i];
        float gterm = g_gterm;
        int n = g_n;
        float local = 0.f;
        #pragma unroll
        for (int k = 0; k < 4; k++) {
            int j = t + k * 256;
            float stau = fabsf(gterm + g_senc[j] - g_cc[j]) * 0.5f;
            float d2 = fmaxf(sen_i + g_pp[j] - 2.0f * g_Gt[i * M + j], 0.0f);
            float arg = -d2 / stau;
            float dens = 0.0f;
            if (j < n && arg > -85.0f) dens = expf(arg);
            dv[k] = dens;
            local += dens;
        }
        #pragma unroll
        for (int o = 16; o > 0; o >>= 1) local += __shfl_down_sync(0xffffffffu, local, o);
        if ((t & 31) == 0) red[t >> 5] = local;
    }
    __syncthreads();
    if (t >= 64 && t < 128) {
        int o = t - 64;
        float z = ynp[0][o] + ynp[1][o] + ynp[2][o] + ynp[3][o] + b[o];
        yn_f[o] = 1.0f / (1.0f + expf(-z));
    }
    if (flag && t < 8) {
        float v = red[t];
        #pragma unroll
        for (int o = 4; o > 0; o >>= 1) v += __shfl_down_sync(0xffu, v, o);
        if (t == 0) s_inv = 1.0f / v;
    }
    __syncthreads();
    if (flag) {
        float inv = s_inv;
        #pragma unroll
        for (int k = 0; k < 4; k++) lam_s[t + k * 256] = dv[k] * inv;
        __syncthreads();
    }
    // --- store 16384 float4 for this row; yn index (f&15)==t&15 is loop-invariant ---
    const float4* yn4 = reinterpret_cast<const float4*>(yn_f);
    float4 base = yn4[t & 15];
    float4* dst = out + (size_t)i * 16384 + t;
    int r0 = t >> 4;
    if (!flag) {
        // lambda == identity: rule-block i gets y_n, everything else zero
        float4 z4 = make_float4(0.f, 0.f, 0.f, 0.f);
        int hit = (r0 == (i & 15)) ? (i >> 4) : -1;
        #pragma unroll
        for (int k = 0; k < 64; k++) {
            float4 v = (k == hit) ? base : z4;
            __stcs(dst + 256 * k, v);        // streaming store: write-once data
        }
    } else {
        #pragma unroll
        for (int k = 0; k < 64; k++) {
            float l = lam_s[r0 + 16 * k];
            float4 v;
            v.x = base.x * l; v.y = base.y * l; v.z = base.z * l; v.w = base.w * l;
            __stcs(dst + 256 * k, v);
        }
    }
}

// ------------------------- launch -------------------------
extern "C" void kernel_launch(void* const* d_in, const int* in_sizes, int n_in,
                              void* d_out, int out_size) {
    const float* x = (const float*)d_in[0];
    const float* W = (const float*)d_in[1];
    const float* b = (const float*)d_in[2];
    float4* out = (float4*)d_out;

    k_sen<<<B / 8, 256>>>(x);
    k_gterm<<<1, 1024>>>(x);
    k_verify<<<528, 256>>>(x);
    k_scan_fallback<<<1, 1024>>>(x);
    k_lamout<<<B, 256>>>(x, W, b, out);
}